// round 9
// baseline (speedup 1.0000x reference)
#include <cuda_runtime.h>
#include <cuda_fp16.h>
#include <cstdint>
#include <math.h>

// ---------------- problem constants ----------------
#define NB    64
#define NCH   64
#define NI    256
#define NKTOT 576          // 64 ch * 9 taps ; reordered k' = r*64 + c
#define PADW  66           // (H+2) halo for pad-1
#define LNK   6.35610766f  // ln(576)

// ---------------- GEMM tiling ----------------
// CTA tile 128(M) x 128(N); stage = { A 16KB | B 16KB }
#define STAGES   3
#define BOFF     16384
#define STG_SZ   32768
#define SMEM_TOTAL (STAGES * STG_SZ)            // 98304 -> 2 CTAs/SM
#define NTHR     128

// ---------------- device scratch (allocation-free rule) ----------------
__device__ __align__(16) __half g_eh[(size_t)NB * PADW * PADW * NCH]; // exp(x) fp16
__device__ __align__(16) __half g_Bh[NI * NKTOT];                     // exp(off) fp16 [i][r*64+c]

// ---------------- helpers ----------------
__device__ __forceinline__ uint32_t smem_u32(const void* p) {
    uint32_t a;
    asm("{ .reg .u64 t; cvta.to.shared.u64 t, %1; cvt.u32.u64 %0, t; }" : "=r"(a) : "l"(p));
    return a;
}
__device__ __forceinline__ uint32_t swz(uint32_t o) { return o ^ ((o >> 3) & 0x70); }

__device__ __forceinline__ void cp16(uint32_t dst, const void* src) {
    asm volatile("cp.async.cg.shared.global [%0], [%1], 16;" :: "r"(dst), "l"(src));
}

#define LDSM4(r, a)                                                                     \
    asm volatile("ldmatrix.sync.aligned.m8n8.x4.shared.b16 {%0,%1,%2,%3}, [%4];"        \
        : "=r"((r)[0]), "=r"((r)[1]), "=r"((r)[2]), "=r"((r)[3]) : "r"(a))

#define MMA16816(d, a, b0, b1)                                                          \
    asm volatile("mma.sync.aligned.m16n8k16.row.col.f32.f16.f16.f32 "                   \
        "{%0,%1,%2,%3}, {%4,%5,%6,%7}, {%8,%9}, {%0,%1,%2,%3};"                         \
        : "+f"((d)[0]), "+f"((d)[1]), "+f"((d)[2]), "+f"((d)[3])                        \
        : "r"((a)[0]), "r"((a)[1]), "r"((a)[2]), "r"((a)[3]), "r"(b0), "r"(b1))

// ===========================================================================
// Prep A: exp(x) fp16 transpose (B,C,H,W)->(B,H+2,W+2,C), borders fused.
// Block = (h2, b): two input rows h = 2*h2, 2*h2+1.
// ===========================================================================
__global__ void k_prep_x(const float* __restrict__ x) {
    __shared__ float tile[2][64][66];          // [hh][w][c]
    const int b = blockIdx.y, h0 = blockIdx.x * 2, t = threadIdx.x;

    __half2* eh2 = reinterpret_cast<__half2*>(g_eh);

#pragma unroll
    for (int i = 0; i < 32; ++i) {
        int idx = t + i * 256;                 // 8192 floats
        int hh = idx >> 12;
        int c  = (idx >> 6) & 63, w = idx & 63;
        tile[hh][w][c] = x[(((size_t)(b * 64 + c) * 64 + (h0 + hh)) << 6) + w];
    }
    __syncthreads();
#pragma unroll
    for (int i = 0; i < 16; ++i) {
        int idx = t + i * 256;                 // 4096 half2's
        int hh = idx >> 11;
        int w  = (idx >> 5) & 63, c2 = idx & 31;
        float2 v = *reinterpret_cast<const float2*>(&tile[hh][w][2 * c2]);
        size_t off2 = ((((size_t)b * PADW + (h0 + hh + 1)) * PADW + (w + 1)) << 5) + c2;
        eh2[off2] = __floats2half2_rn(__expf(v.x), __expf(v.y));
    }

    // left halo col (w=0) for this block's two rows: 2*32 half2
    if (t < 64) {
        int hh = t >> 5, c2 = t & 31;
        size_t off2 = ((((size_t)b * PADW + (h0 + hh + 1)) * PADW + 0) << 5) + c2;
        eh2[off2] = __floats2half2_rn(1.0f, 1.0f);
    }
    // top halo row (h index 0), painted by h2==0 blocks: 66*32 = 2112 half2
    if (blockIdx.x == 0) {
#pragma unroll
        for (int i = 0; i < 9; ++i) {
            int idx = t + i * 256;
            if (idx < PADW * 32) {
                int pos = idx >> 5, c2 = idx & 31;
                size_t off2 = ((((size_t)b * PADW + 0) * PADW + pos) << 5) + c2;
                eh2[off2] = __floats2half2_rn(1.0f, 1.0f);
            }
        }
    }
}

// ===========================================================================
// Prep B: exp(offsets) fp16, reorder k = c*9+r  ->  k' = r*64+c
// ===========================================================================
__global__ void k_prep_o(const float* __restrict__ off) {
    int t = blockIdx.x * 256 + threadIdx.x;  // < 256*576 = 147456
    int i  = t / NKTOT;
    int kp = t - i * NKTOT;
    int r = kp >> 6, c = kp & 63;
    g_Bh[t] = __float2half_rn(__expf(off[i * NKTOT + c * 9 + r]));
}

// ===========================================================================
// Main GEMM: CTA 128(M) x 128(N), 4 warps 2x2, warp tile 64x64.
// Single fp16 pass, 9 taps (K-chunks of 64). 2 CTAs/SM, 3-stage pipeline.
// ===========================================================================
__device__ __forceinline__ void load_chunk(int r, int s, uint32_t smb,
                                           int tid, int bb, int ohb, int nbase) {
    int fh = r / 3, fw = r - fh * 3;
    uint32_t sa = smb + s * STG_SZ;
    uint32_t sb = sa + BOFF;
    // A tile: 128 rows x 8 segs = 1024 x 16B
#pragma unroll
    for (int it = 0; it < 8; ++it) {
        int idx = tid + it * NTHR;
        int l = idx >> 3, g = idx & 7;
        int ih1 = 2 * ohb + ((l >> 5) << 1) + fh;   // (oh*2-1+fh)+1
        int iw1 = ((l & 31) << 1) + fw;             // (ow*2-1+fw)+1
        size_t eo = ((((size_t)bb * PADW + ih1) * PADW + iw1) << 6) + (g << 3);
        cp16(sa + swz((l << 7) + (g << 4)), g_eh + eo);
    }
    // B tile: 128 rows x 8 segs = 1024 x 16B
#pragma unroll
    for (int it = 0; it < 8; ++it) {
        int idx = tid + it * NTHR;
        int n = idx >> 3, g = idx & 7;
        const void* src = g_Bh + (size_t)(nbase + n) * NKTOT + (r << 6) + (g << 3);
        cp16(sb + swz((n << 7) + (g << 4)), src);
    }
    asm volatile("cp.async.commit_group;" ::: "memory");
}

__global__ void __launch_bounds__(NTHR, 2) k_mex(float* __restrict__ out) {
    extern __shared__ __align__(1024) char sm[];
    const uint32_t smb = smem_u32(sm);
    const int tid  = threadIdx.x;
    const int wid  = tid >> 5, lane = tid & 31;
    const int bx   = blockIdx.x;
    const int bb   = bx >> 4;                   // batch
    const int ohb  = ((bx >> 1) & 7) << 2;      // 4 output rows per tile
    const int nbase = (bx & 1) << 7;            // instance half
    const int wm   = wid >> 1;                  // 0..1  (m block of 64)
    const int wn   = wid & 1;                   // 0..1  (n block of 64)

    float acc[4][8][4];                          // [mt][n8 tile][d-regs]
#pragma unroll
    for (int a = 0; a < 4; ++a)
#pragma unroll
        for (int b = 0; b < 8; ++b)
#pragma unroll
            for (int c = 0; c < 4; ++c) acc[a][b][c] = 0.0f;

    // per-lane ldmatrix address components
    const int rowA_l = (lane & 7) + (lane & 8);        // + mt*16 + wm*64
    const int segA_l = (lane & 16);                    // + ks*32
    const int rowB_l = (lane & 7) + ((lane & 16) >> 1);// + jj*16 + wn*64
    const int segB_l = ((lane & 8) << 1);              // + ks*32

    // prologue: prefetch taps 0,1
    load_chunk(0, 0, smb, tid, bb, ohb, nbase);
    load_chunk(1, 1, smb, tid, bb, ohb, nbase);

#pragma unroll 1
    for (int j = 0; j < 9; ++j) {
        if (j < 8) asm volatile("cp.async.wait_group 1;" ::: "memory");
        else       asm volatile("cp.async.wait_group 0;" ::: "memory");
        __syncthreads();     // chunk j ready; all warps done with chunk j-1

        if (j + 2 < 9) load_chunk(j + 2, (j + 2) % 3, smb, tid, bb, ohb, nbase);

        const uint32_t sa = smb + (j % 3) * STG_SZ;
        const uint32_t sb = sa + BOFF;

#pragma unroll
        for (int ks = 0; ks < 4; ++ks) {
            uint32_t bf[4][4];
#pragma unroll
            for (int jj = 0; jj < 4; ++jj) {
                int row = wn * 64 + jj * 16 + rowB_l;
                uint32_t byo = (uint32_t)(ks * 32 + segB_l) ^ ((row & 7) << 4);
                LDSM4(bf[jj], sb + row * 128 + byo);
            }
#pragma unroll
            for (int mt = 0; mt < 4; ++mt) {
                int row = wm * 64 + mt * 16 + rowA_l;
                uint32_t byo = (uint32_t)(ks * 32 + segA_l) ^ ((row & 7) << 4);
                uint32_t af[4];
                LDSM4(af, sa + row * 128 + byo);
#pragma unroll
                for (int jj = 0; jj < 4; ++jj) {
                    MMA16816(acc[mt][2 * jj],     af, bf[jj][0], bf[jj][1]);
                    MMA16816(acc[mt][2 * jj + 1], af, bf[jj][2], bf[jj][3]);
                }
            }
        }
    }

    // epilogue: y = log(S) - ln(576); out layout (B, NI, 32, 32)
    const int g  = lane >> 2;
    const int tc = lane & 3;
    float* ob = out + ((size_t)bb << 18);
#pragma unroll
    for (int mt = 0; mt < 4; ++mt) {
#pragma unroll
        for (int jj = 0; jj < 8; ++jj) {
            const int i0 = nbase + wn * 64 + jj * 8 + 2 * tc;
#pragma unroll
            for (int r = 0; r < 4; ++r) {
                int m = wm * 64 + mt * 16 + g + ((r >> 1) << 3);
                int i = i0 + (r & 1);
                float y = __logf(acc[mt][jj][r]) - LNK;
                ob[((size_t)i << 10) + ((ohb + (m >> 5)) << 5) + (m & 31)] = y;
            }
        }
    }
}

// ===========================================================================
extern "C" void kernel_launch(void* const* d_in, const int* in_sizes, int n_in,
                              void* d_out, int out_size) {
    const float* x   = (const float*)d_in[0];   // (64,64,64,64)
    const float* off = (const float*)d_in[1];   // (1,256,64,3,3)
    float* out       = (float*)d_out;           // (64,256,32,32)

    k_prep_o<<<576, 256>>>(off);
    dim3 gx(32, 64);                            // (h/2, b)
    k_prep_x<<<gx, 256>>>(x);

    cudaFuncSetAttribute(k_mex, cudaFuncAttributeMaxDynamicSharedMemorySize, SMEM_TOTAL);
    k_mex<<<1024, NTHR, SMEM_TOTAL>>>(out);
}

// round 10
// speedup vs baseline: 1.0493x; 1.0493x over previous
#include <cuda_runtime.h>
#include <cuda_fp16.h>
#include <cstdint>
#include <math.h>

// ---------------- problem constants ----------------
#define NB    64
#define NCH   64
#define NI    256
#define NKTOT 576          // 64 ch * 9 taps ; reordered k' = r*64 + c
#define PADW  66           // (H+2) halo for pad-1
#define LNK   6.35610766f  // ln(576)

// ---------------- GEMM smem layout ----------------
// footprint A: 9 rows x 65 cols x 128B (per-pixel channel vectors, XOR-swizzled)
// B: 2 stages x 16KB (SW128-swizzled 128x64 fp16 tiles)
#define FP_SEGS  4680      // 9*65*8 segments of 16B
#define B_OFF    75776     // 74880 rounded up to 1024
#define B_STG    16384
#define SMEM_TOTAL (B_OFF + 2 * B_STG)   // 108544 -> 2 CTAs/SM
#define NTHR     128

// ---------------- device scratch (allocation-free rule) ----------------
__device__ __align__(16) __half g_eh[(size_t)NB * PADW * PADW * NCH]; // exp(x) fp16
__device__ __align__(16) __half g_Bh[NI * NKTOT];                     // exp(off) fp16 [i][r*64+c]

// ---------------- helpers ----------------
__device__ __forceinline__ uint32_t smem_u32(const void* p) {
    uint32_t a;
    asm("{ .reg .u64 t; cvta.to.shared.u64 t, %1; cvt.u32.u64 %0, t; }" : "=r"(a) : "l"(p));
    return a;
}
__device__ __forceinline__ uint32_t swz(uint32_t o) { return o ^ ((o >> 3) & 0x70); }

__device__ __forceinline__ void cp16(uint32_t dst, const void* src) {
    asm volatile("cp.async.cg.shared.global [%0], [%1], 16;" :: "r"(dst), "l"(src));
}

#define LDSM4(r, a)                                                                     \
    asm volatile("ldmatrix.sync.aligned.m8n8.x4.shared.b16 {%0,%1,%2,%3}, [%4];"        \
        : "=r"((r)[0]), "=r"((r)[1]), "=r"((r)[2]), "=r"((r)[3]) : "r"(a))

#define MMA16816(d, a, b0, b1)                                                          \
    asm volatile("mma.sync.aligned.m16n8k16.row.col.f32.f16.f16.f32 "                   \
        "{%0,%1,%2,%3}, {%4,%5,%6,%7}, {%8,%9}, {%0,%1,%2,%3};"                         \
        : "+f"((d)[0]), "+f"((d)[1]), "+f"((d)[2]), "+f"((d)[3])                        \
        : "r"((a)[0]), "r"((a)[1]), "r"((a)[2]), "r"((a)[3]), "r"(b0), "r"(b1))

// ===========================================================================
// Fused prep: blocks [0,4096): exp(x)+transpose (+halo paint);
//             blocks [4096,4672): exp(offsets) reorder.
// ===========================================================================
__global__ void k_prep(const float* __restrict__ x, const float* __restrict__ off) {
    const int bx = blockIdx.x, t = threadIdx.x;

    if (bx >= 4096) {           // ---- offsets part
        int tt = (bx - 4096) * 256 + t;    // < 147456
        int i  = tt / NKTOT;
        int kp = tt - i * NKTOT;
        int r = kp >> 6, c = kp & 63;
        g_Bh[tt] = __float2half_rn(__expf(off[i * NKTOT + c * 9 + r]));
        return;
    }

    // ---- x part: one input row h of one batch b
    __shared__ float tile[64][66];          // [w][c]
    const int b = bx >> 6, h = bx & 63;
    __half2* eh2 = reinterpret_cast<__half2*>(g_eh);

#pragma unroll
    for (int i = 0; i < 16; ++i) {
        int idx = t + i * 256;
        int c = idx >> 6, w = idx & 63;
        tile[w][c] = x[(((size_t)(b * 64 + c) * 64 + h) << 6) + w];
    }
    __syncthreads();
#pragma unroll
    for (int i = 0; i < 8; ++i) {
        int idx = t + i * 256;              // 2048 half2's
        int w = idx >> 5, c2 = idx & 31;
        float2 v = *reinterpret_cast<const float2*>(&tile[w][2 * c2]);
        size_t off2 = ((((size_t)b * PADW + (h + 1)) * PADW + (w + 1)) << 5) + c2;
        eh2[off2] = __floats2half2_rn(__expf(v.x), __expf(v.y));
    }
    // left halo (w=0) for this row
    if (t < 32) {
        size_t off2 = ((((size_t)b * PADW + (h + 1)) * PADW + 0) << 5) + t;
        eh2[off2] = __floats2half2_rn(1.0f, 1.0f);
    }
    // top halo row, painted by h==0 blocks: 66*32 = 2112 half2
    if (h == 0) {
#pragma unroll
        for (int i = 0; i < 9; ++i) {
            int idx = t + i * 256;
            if (idx < PADW * 32) {
                int pos = idx >> 5, c2 = idx & 31;
                size_t off2 = ((((size_t)b * PADW + 0) * PADW + pos) << 5) + c2;
                eh2[off2] = __floats2half2_rn(1.0f, 1.0f);
            }
        }
    }
}

// ===========================================================================
// Main GEMM: CTA 128(M) x 128(N), 4 warps 2x2, warp tile 64x64.
// A kept as a 9x65 pixel footprint in smem (loaded once); per-tap A fragments
// gathered via per-lane ldmatrix addresses. B double-buffered per tap.
// ===========================================================================
__device__ __forceinline__ void load_B(int r, int s, uint32_t smb,
                                       int tid, int nbase) {
    uint32_t sb = smb + B_OFF + s * B_STG;
#pragma unroll
    for (int it = 0; it < 8; ++it) {
        int idx = tid + it * NTHR;
        int n = idx >> 3, g = idx & 7;
        const void* src = g_Bh + (size_t)(nbase + n) * NKTOT + (r << 6) + (g << 3);
        cp16(sb + swz((n << 7) + (g << 4)), src);
    }
    asm volatile("cp.async.commit_group;" ::: "memory");
}

__global__ void __launch_bounds__(NTHR, 2) k_mex(float* __restrict__ out) {
    extern __shared__ __align__(1024) char sm[];
    const uint32_t smb = smem_u32(sm);
    const int tid  = threadIdx.x;
    const int wid  = tid >> 5, lane = tid & 31;
    const int bx   = blockIdx.x;
    const int bb   = bx >> 4;                   // batch
    const int ohb  = ((bx >> 1) & 7) << 2;      // 4 output rows per tile
    const int nbase = (bx & 1) << 7;            // instance half
    const int wm   = wid >> 1;                  // 0..1  (m block of 64)
    const int wn   = wid & 1;                   // 0..1  (n block of 64)

    float acc[4][8][4];                          // [mt][n8 tile][d-regs]
#pragma unroll
    for (int a = 0; a < 4; ++a)
#pragma unroll
        for (int b = 0; b < 8; ++b)
#pragma unroll
            for (int c = 0; c < 4; ++c) acc[a][b][c] = 0.0f;

    // per-lane ldmatrix components
    const int rowA_l = (lane & 7) + (lane & 8);        // row within m16 block
    const int sA     = (lane & 16) >> 4;               // k-seg half (0/1)
    const int rowB_l = (lane & 7) + ((lane & 16) >> 1);// + jj*16 + wn*64
    const int segB_l = ((lane & 8) << 1);              // + ks*32

    // ---- prologue: footprint A (once) + B tap 0, one cp.async group
#pragma unroll 4
    for (int it = 0; it < 37; ++it) {
        int idx = tid + it * NTHR;
        if (idx < FP_SEGS) {
            int g = idx & 7, q = idx >> 3;     // q = L = h*65 + w
            int hq = q / 65, w = q - hq * 65;
            const void* src = g_eh +
                ((((size_t)bb * PADW + (2 * ohb + hq)) * PADW + w) << 6) + (g << 3);
            cp16(smb + (q << 7) + (((g ^ ((q >> 1) & 7)) << 4)), src);
        }
    }
    load_B(0, 0, smb, tid, nbase);   // commits the footprint+B0 group

    // per-thread A m-row constants (per mt): output quad row & column
    int ohq[4], ow2[4];
#pragma unroll
    for (int mt = 0; mt < 4; ++mt) {
        int m = wm * 64 + mt * 16 + rowA_l;
        ohq[mt] = (m >> 5) << 1;               // 2*oh_local
        ow2[mt] = (m & 31) << 1;               // 2*ow
    }

#pragma unroll 1
    for (int j = 0; j < 9; ++j) {
        asm volatile("cp.async.wait_group 0;" ::: "memory");
        __syncthreads();     // B_j (and footprint) visible; all warps done with j-1

        if (j + 1 < 9) load_B(j + 1, (j + 1) & 1, smb, tid, nbase);

        const int fh = j / 3, fw = j - fh * 3;
        const uint32_t sb = smb + B_OFF + (j & 1) * B_STG;

        // per-mt footprint row base + swizzle key for this tap
        uint32_t abase[4];
        int akey[4];
#pragma unroll
        for (int mt = 0; mt < 4; ++mt) {
            int L = (ohq[mt] + fh) * 65 + ow2[mt] + fw;
            abase[mt] = smb + (L << 7);
            akey[mt]  = (L >> 1) & 7;
        }

#pragma unroll
        for (int ks = 0; ks < 4; ++ks) {
            uint32_t bf[4][4];
#pragma unroll
            for (int jj = 0; jj < 4; ++jj) {
                int row = wn * 64 + jj * 16 + rowB_l;
                uint32_t byo = (uint32_t)(ks * 32 + segB_l) ^ ((row & 7) << 4);
                LDSM4(bf[jj], sb + row * 128 + byo);
            }
#pragma unroll
            for (int mt = 0; mt < 4; ++mt) {
                uint32_t af[4];
                uint32_t aoff = (uint32_t)(((2 * ks + sA) ^ akey[mt]) << 4);
                LDSM4(af, abase[mt] + aoff);
#pragma unroll
                for (int jj = 0; jj < 4; ++jj) {
                    MMA16816(acc[mt][2 * jj],     af, bf[jj][0], bf[jj][1]);
                    MMA16816(acc[mt][2 * jj + 1], af, bf[jj][2], bf[jj][3]);
                }
            }
        }
    }

    // epilogue: y = log(S) - ln(576); out layout (B, NI, 32, 32)
    const int g  = lane >> 2;
    const int tc = lane & 3;
    float* ob = out + ((size_t)bb << 18);
#pragma unroll
    for (int mt = 0; mt < 4; ++mt) {
#pragma unroll
        for (int jj = 0; jj < 8; ++jj) {
            const int i0 = nbase + wn * 64 + jj * 8 + 2 * tc;
#pragma unroll
            for (int r = 0; r < 4; ++r) {
                int m = wm * 64 + mt * 16 + g + ((r >> 1) << 3);
                int i = i0 + (r & 1);
                float y = __logf(acc[mt][jj][r]) - LNK;
                ob[((size_t)i << 10) + ((ohb + (m >> 5)) << 5) + (m & 31)] = y;
            }
        }
    }
}

// ===========================================================================
extern "C" void kernel_launch(void* const* d_in, const int* in_sizes, int n_in,
                              void* d_out, int out_size) {
    const float* x   = (const float*)d_in[0];   // (64,64,64,64)
    const float* off = (const float*)d_in[1];   // (1,256,64,3,3)
    float* out       = (float*)d_out;           // (64,256,32,32)

    k_prep<<<4672, 256>>>(x, off);

    cudaFuncSetAttribute(k_mex, cudaFuncAttributeMaxDynamicSharedMemorySize, SMEM_TOTAL);
    k_mex<<<1024, NTHR, SMEM_TOTAL>>>(out);
}